// round 13
// baseline (speedup 1.0000x reference)
#include <cuda_runtime.h>
#include <cuda_bf16.h>

#define NUM_LEVELS 256
#define THREADS 256
#define VPT 4            // float4 vectors per thread (front-batched → MLP_p1 = 4)

__global__ __launch_bounds__(THREADS, 4)
void NeuralQuantizer_7507602833923_kernel(const float4* __restrict__ x,
                                          const float* __restrict__ centers,
                                          float4* __restrict__ out,
                                          int n4) {
    // 32-way replicated codebook: cen_r[k*32 + lane] -> lane always hits its own
    // bank, so the random gathers below are conflict-free (N=1).
    __shared__ float cen_r[NUM_LEVELS * 32];
    #pragma unroll
    for (int j = threadIdx.x; j < NUM_LEVELS * 32; j += THREADS)
        cen_r[j] = centers[j >> 5];
    __syncthreads();

    const int lane = threadIdx.x & 31;
    const float* __restrict__ myc = cen_r + lane;   // index with k*32

    const float inv_step = 127.5f;   // (NUM_LEVELS-1)/2 for linspace(-1,1,256)

    const int g = blockIdx.x * THREADS + threadIdx.x;
    const int stride = gridDim.x * THREADS;

    // Front-batch all 4 independent 128-bit loads (streaming: no reuse).
    float4 v[VPT];
    #pragma unroll
    for (int u = 0; u < VPT; ++u) {
        int idx = g + u * stride;
        if (idx < n4) v[u] = __ldcs(&x[idx]);
    }

    #pragma unroll
    for (int u = 0; u < VPT; ++u) {
        int idx = g + u * stride;
        if (idx >= n4) continue;

        float4 r;
        float* vp = reinterpret_cast<float*>(&v[u]);
        float* rp = reinterpret_cast<float*>(&r);

        #pragma unroll
        for (int j = 0; j < 4; ++j) {
            float xv = vp[j];
            // Analytic nearest-center candidate (centers uniform in [-1,1]).
            float t = fmaf(xv, inv_step, inv_step);       // (x+1)*127.5
            int k = (int)floorf(t + 0.5f);
            k = max(0, min(NUM_LEVELS - 1, k));

            // Exact argmin tie-break against the REAL center values (fp32
            // distances, ties -> lowest index, matching jnp.argmin).
            float ck = myc[k * 32];
            float dk = fabsf(xv - ck);
            if (k > 0) {
                float cm = myc[(k - 1) * 32];
                float dm = fabsf(xv - cm);
                if (dm <= dk) { k -= 1; ck = cm; dk = dm; }
            }
            if (k < NUM_LEVELS - 1) {
                float cp = myc[(k + 1) * 32];
                float dp = fabsf(xv - cp);
                if (dp < dk) { ck = cp; }
            }
            rp[j] = ck;   // forward value of the STE is just centers[k]
        }

        __stcs(&out[idx], r);
    }
}

extern "C" void kernel_launch(void* const* d_in, const int* in_sizes, int n_in,
                              void* d_out, int out_size) {
    const float4* x      = (const float4*)d_in[0];
    const float* centers = (const float*)d_in[1];
    float4* out          = (float4*)d_out;

    int n  = in_sizes[0];     // 2,097,152 floats
    int n4 = n / 4;           // 524,288 float4 vectors

    int blocks = (n4 + THREADS * VPT - 1) / (THREADS * VPT);   // 512
    NeuralQuantizer_7507602833923_kernel<<<blocks, THREADS>>>(x, centers, out, n4);
}

// round 14
// speedup vs baseline: 1.2316x; 1.2316x over previous
#include <cuda_runtime.h>
#include <cuda_bf16.h>
#include <math_constants.h>

#define NUM_LEVELS 256
#define THREADS 256
#define VPT 2            // float4 vectors per thread, front-batched (MLP_p1 = 2)

__global__ __launch_bounds__(THREADS)
void NeuralQuantizer_7507602833923_kernel(const float4* __restrict__ x,
                                          const float* __restrict__ centers,
                                          float4* __restrict__ out,
                                          int n4) {
    // One LDS.128 per element fetches (cen[k-1], cen[k], cen[k+1]).
    // +INF sentinels at the edges make the missing neighbor self-excluding
    // (its distance is INF, so it never wins a comparison).
    __shared__ float4 cen4[NUM_LEVELS];
    {
        int k = threadIdx.x;                       // THREADS == NUM_LEVELS
        float cm = (k > 0)              ? centers[k - 1] : CUDART_INF_F;
        float ck = centers[k];
        float cp = (k < NUM_LEVELS - 1) ? centers[k + 1] : CUDART_INF_F;
        cen4[k] = make_float4(cm, ck, cp, 0.0f);
    }
    __syncthreads();

    const float inv_step = 127.5f;   // (NUM_LEVELS-1)/2 for linspace(-1,1,256)

    const int g = blockIdx.x * THREADS + threadIdx.x;
    const int stride = gridDim.x * THREADS;

    // Front-batch the independent 128-bit loads.
    float4 v[VPT];
    #pragma unroll
    for (int u = 0; u < VPT; ++u) {
        int idx = g + u * stride;
        if (idx < n4) v[u] = x[idx];
    }

    #pragma unroll
    for (int u = 0; u < VPT; ++u) {
        int idx = g + u * stride;
        if (idx >= n4) continue;

        float4 r;
        float* vp = reinterpret_cast<float*>(&v[u]);
        float* rp = reinterpret_cast<float*>(&r);

        #pragma unroll
        for (int j = 0; j < 4; ++j) {
            float xv = vp[j];
            // Analytic nearest-center candidate (centers uniform in [-1,1]).
            float t = fmaf(xv, inv_step, inv_step);       // (x+1)*127.5
            int k = __float2int_rn(t);
            k = max(0, min(NUM_LEVELS - 1, k));

            // One wide gather: the candidate and both neighbors.
            float4 c = cen4[k];

            // Exact argmin among {k-1, k, k+1} on fp32 distances to the REAL
            // center values, ties -> lowest index (matches jnp.argmin):
            //   pick m  iff dm <= dk && dm <= dp
            //   else k  iff dk <= dp
            //   else p
            float dm = fabsf(xv - c.x);
            float dk = fabsf(xv - c.y);
            float dp = fabsf(xv - c.z);

            float a  = (dk <= dp) ? c.y : c.z;
            rp[j] = (dm <= dk && dm <= dp) ? c.x : a;
        }

        out[idx] = r;
    }
}

extern "C" void kernel_launch(void* const* d_in, const int* in_sizes, int n_in,
                              void* d_out, int out_size) {
    const float4* x      = (const float4*)d_in[0];
    const float* centers = (const float*)d_in[1];
    float4* out          = (float4*)d_out;

    int n  = in_sizes[0];     // 2,097,152 floats
    int n4 = n / 4;           // 524,288 float4 vectors

    int blocks = (n4 + THREADS * VPT - 1) / (THREADS * VPT);   // 1024
    NeuralQuantizer_7507602833923_kernel<<<blocks, THREADS>>>(x, centers, out, n4);
}